// round 14
// baseline (speedup 1.0000x reference)
#include <cuda_runtime.h>
#include <cuda_bf16.h>
#include <math.h>
#include <stdint.h>

#define SEQ   1024
#define EMB   1024
#define BATCH 2
#define MHEAD 16      // total heads (M*H)
#define HD    64      // head dim
#define E3    (3*EMB)

// ---------------- scratch (allocation-free rule: __device__ globals) --------
__device__ __nv_bfloat16 g_xh [(size_t)2048*1024], g_xl [(size_t)2048*1024];
__device__ __nv_bfloat16 g_wqh[(size_t)3072*1024], g_wql[(size_t)3072*1024];
__device__ __nv_bfloat16 g_wph[(size_t)1024*1024], g_wpl[(size_t)1024*1024];
__device__ __nv_bfloat16 g_qkh[(size_t)2048*2048], g_qkl[(size_t)2048*2048];  // Q|K
__device__ __nv_bfloat16 g_vth[(size_t)32*64*1024], g_vtl[(size_t)32*64*1024]; // V^T [bh][c][k]
__device__ __nv_bfloat16 g_aoh[(size_t)2048*1024], g_aol[(size_t)2048*1024];

// ===================== helpers ==============================================
__device__ __forceinline__ uint32_t smem_u32(const void* p) {
    uint32_t a;
    asm("{ .reg .u64 t; cvta.to.shared.u64 t, %1; cvt.u32.u64 %0, t; }"
        : "=r"(a) : "l"(p));
    return a;
}
__device__ __forceinline__ void ldsm4(uint32_t* r, uint32_t addr) {
    asm volatile("ldmatrix.sync.aligned.m8n8.x4.shared.b16 {%0,%1,%2,%3}, [%4];"
                 : "=r"(r[0]), "=r"(r[1]), "=r"(r[2]), "=r"(r[3]) : "r"(addr));
}
__device__ __forceinline__ void mma16816(float* d, const uint32_t* a,
                                         const uint32_t* b) {
    asm volatile("mma.sync.aligned.m16n8k16.row.col.f32.bf16.bf16.f32 "
                 "{%0,%1,%2,%3}, {%4,%5,%6,%7}, {%8,%9}, {%0,%1,%2,%3};"
                 : "+f"(d[0]), "+f"(d[1]), "+f"(d[2]), "+f"(d[3])
                 : "r"(a[0]), "r"(a[1]), "r"(a[2]), "r"(a[3]),
                   "r"(b[0]), "r"(b[1]));
}
__device__ __forceinline__ uint32_t pack_bf16(float x, float y) {
    __nv_bfloat162 p;
    p.x = __float2bfloat16(x);
    p.y = __float2bfloat16(y);
    return *(uint32_t*)&p;
}
__device__ __forceinline__ void split_lo(uint32_t hi, float x, float y,
                                         uint32_t* lo) {
    __nv_bfloat162* h = (__nv_bfloat162*)&hi;
    *lo = pack_bf16(x - __bfloat162float(h->x), y - __bfloat162float(h->y));
}
__device__ __forceinline__ void cp16(uint32_t saddr, const void* g) {
    asm volatile("cp.async.cg.shared.global [%0], [%1], 16;"
                 :: "r"(saddr), "l"(g));
}
#define CP_COMMIT() asm volatile("cp.async.commit_group;" ::: "memory")
#define CP_WAIT1()  asm volatile("cp.async.wait_group 1;" ::: "memory")
#define CP_WAIT0()  asm volatile("cp.async.wait_group 0;" ::: "memory")

// ---------------- pre-pass: fp32 -> bf16 hi/lo split ------------------------
__global__ void __launch_bounds__(256)
split_f32(const float* __restrict__ s, __nv_bfloat16* __restrict__ h,
          __nv_bfloat16* __restrict__ l) {
    size_t i = ((size_t)blockIdx.x * 256 + threadIdx.x) * 4;
    float4 v = *(const float4*)&s[i];
    uint32_t h0 = pack_bf16(v.x, v.y), h1 = pack_bf16(v.z, v.w);
    uint32_t l0, l1;
    split_lo(h0, v.x, v.y, &l0);
    split_lo(h1, v.z, v.w, &l1);
    *(uint2*)&h[i] = make_uint2(h0, h1);
    *(uint2*)&l[i] = make_uint2(l0, l1);
}

#define PADK 40      // bf16 elements per smem row (32 data + 8 pad) = 80 bytes

// ========== bf16x3 NT GEMM, cp.async double-buffered ========================
// Block tile 128x64, K-chunk 32, 2 smem stages. 8 warps: 4(m) x 2(n).
// stage layout (bytes): AH 0, AL 10240, BH 20480, BL 25600; stage size 30720
#define GS_AH 0
#define GS_AL 10240
#define GS_BH 20480
#define GS_BL 25600
#define GS_STAGE 30720
#define GS_TOTAL 61440

template<int EPI>
__global__ void __launch_bounds__(256, 2)
gemm_pre(const __nv_bfloat16* __restrict__ Ah, const __nv_bfloat16* __restrict__ Al,
         const __nv_bfloat16* __restrict__ Bh, const __nv_bfloat16* __restrict__ Bl,
         float* __restrict__ C, int N, int K) {
    extern __shared__ char sm[];
    const uint32_t sb = smem_u32(sm);
    const int tid = threadIdx.x, lane = tid & 31, wid = tid >> 5;
    const int wm = wid & 3, wn = wid >> 2;
    const int bm = blockIdx.y * 128, bn = blockIdx.x * 64;

    // per-thread copy coordinates
    const int arow0 = tid >> 2, ac8 = tid & 3;        // A: 2 rows apart by 64
    const int brow0 = tid >> 2, bc8 = tid & 3;        // B: 1 row set

    auto prefetch = [&](int ch, int stg) {
        const int kt = ch * 32;
        const uint32_t base = sb + stg * GS_STAGE;
        #pragma unroll
        for (int j = 0; j < 2; j++) {
            int row = arow0 + j * 64;
            uint32_t off = (uint32_t)(row * 80 + ac8 * 16);
            const size_t g = (size_t)(bm + row) * K + kt + ac8 * 8;
            cp16(base + GS_AH + off, &Ah[g]);
            cp16(base + GS_AL + off, &Al[g]);
        }
        {
            uint32_t off = (uint32_t)(brow0 * 80 + bc8 * 16);
            const size_t g = (size_t)(bn + brow0) * K + kt + bc8 * 8;
            cp16(base + GS_BH + off, &Bh[g]);
            cp16(base + GS_BL + off, &Bl[g]);
        }
    };

    float acc[2][4][4] = {};
    const int nch = K / 32;
    prefetch(0, 0);
    CP_COMMIT();

    for (int ch = 0; ch < nch; ch++) {
        if (ch + 1 < nch) {
            prefetch(ch + 1, (ch + 1) & 1);
            CP_COMMIT();
            CP_WAIT1();
        } else {
            CP_WAIT0();
        }
        __syncthreads();

        const uint32_t stg = sb + (ch & 1) * GS_STAGE;
        #pragma unroll
        for (int ks = 0; ks < 2; ks++) {
            uint32_t ahf[2][4], alf[2][4];
            const int arow = wm * 32 + (lane & 15);
            const int acol = ks * 16 + (lane >> 4) * 8;
            #pragma unroll
            for (int mf = 0; mf < 2; mf++) {
                uint32_t ad = (uint32_t)((arow + mf * 16) * 80 + acol * 2);
                ldsm4(ahf[mf], stg + GS_AH + ad);
                ldsm4(alf[mf], stg + GS_AL + ad);
            }
            const int brow = wn * 32 + ((lane >> 4) << 3) + (lane & 7);
            const int bcol = ks * 16 + ((lane >> 3) & 1) * 8;
            #pragma unroll
            for (int nf2 = 0; nf2 < 2; nf2++) {
                uint32_t bd = (uint32_t)((brow + nf2 * 16) * 80 + bcol * 2);
                uint32_t bhf[4], blf[4];
                ldsm4(bhf, stg + GS_BH + bd);
                ldsm4(blf, stg + GS_BL + bd);
                #pragma unroll
                for (int h = 0; h < 2; h++) {
                    #pragma unroll
                    for (int mf = 0; mf < 2; mf++) {
                        float* d = acc[mf][nf2 * 2 + h];
                        mma16816(d, ahf[mf], bhf + 2 * h);
                        mma16816(d, ahf[mf], blf + 2 * h);
                        mma16816(d, alf[mf], bhf + 2 * h);
                    }
                }
            }
        }
        __syncthreads();
    }

    if (EPI == 0) {
        #pragma unroll
        for (int mf = 0; mf < 2; mf++) {
            const int r = bm + wm * 32 + mf * 16 + (lane >> 2);
            #pragma unroll
            for (int nf = 0; nf < 4; nf++) {
                const int c = bn + wn * 32 + nf * 8 + (lane & 3) * 2;
                *(float2*)&C[(size_t)r * N + c] =
                    make_float2(acc[mf][nf][0], acc[mf][nf][1]);
                *(float2*)&C[(size_t)(r + 8) * N + c] =
                    make_float2(acc[mf][nf][2], acc[mf][nf][3]);
            }
        }
    } else if (bn < 2048) {
        // Q|K region: hi/lo bf16, row stride 2048
        #pragma unroll
        for (int mf = 0; mf < 2; mf++) {
            const int r = bm + wm * 32 + mf * 16 + (lane >> 2);
            #pragma unroll
            for (int nf = 0; nf < 4; nf++) {
                const int c = bn + wn * 32 + nf * 8 + (lane & 3) * 2;
                float a0 = acc[mf][nf][0], a1 = acc[mf][nf][1];
                uint32_t h = pack_bf16(a0, a1), lo;
                split_lo(h, a0, a1, &lo);
                *(uint32_t*)&g_qkh[(size_t)r * 2048 + c] = h;
                *(uint32_t*)&g_qkl[(size_t)r * 2048 + c] = lo;
                a0 = acc[mf][nf][2]; a1 = acc[mf][nf][3];
                h = pack_bf16(a0, a1);
                split_lo(h, a0, a1, &lo);
                *(uint32_t*)&g_qkh[(size_t)(r + 8) * 2048 + c] = h;
                *(uint32_t*)&g_qkl[(size_t)(r + 8) * 2048 + c] = lo;
            }
        }
    } else {
        // V region: write transposed hi/lo  g_vt[bh][c][k]
        #pragma unroll
        for (int mf = 0; mf < 2; mf++) {
            const int r = bm + wm * 32 + mf * 16 + (lane >> 2);
            const int bnum = r >> 10, k1 = r & 1023, k2 = (r + 8) & 1023;
            #pragma unroll
            for (int nf = 0; nf < 4; nf++) {
                #pragma unroll
                for (int e = 0; e < 2; e++) {
                    const int cm = bn + wn * 32 + nf * 8 + (lane & 3) * 2 + e
                                   - 2048;
                    const size_t rb =
                        ((size_t)(bnum * 16 + (cm >> 6)) * 64 + (cm & 63)) * 1024;
                    float v0 = acc[mf][nf][e], v1 = acc[mf][nf][2 + e];
                    __nv_bfloat16 h0 = __float2bfloat16(v0);
                    g_vth[rb + k1] = h0;
                    g_vtl[rb + k1] =
                        __float2bfloat16(v0 - __bfloat162float(h0));
                    __nv_bfloat16 h1 = __float2bfloat16(v1);
                    g_vth[rb + k2] = h1;
                    g_vtl[rb + k2] =
                        __float2bfloat16(v1 - __bfloat162float(h1));
                }
            }
        }
    }
}

// ========== fused flash attention, cp.async double-buffered K/V =============
// grid (S/64 q-tiles, B*MHEAD), 128 threads (4 warps x 16 q-rows).
#define SQPAD 72            // rows: 64 cols + 8 pad (bf16), 144B stride
#define FQ_H 0
#define FQ_L 9216
#define FKV_BASE 18432      // stage s at FKV_BASE + s*36864
#define FS_KH 0
#define FS_KL 9216
#define FS_VH 18432
#define FS_VL 27648
#define FS_STAGE 36864
#define FO_TOTAL 92160

__global__ void __launch_bounds__(128, 2)
flash_att(const int* __restrict__ mask_head, const int* __restrict__ mask_child,
          float* __restrict__ arc) {
    extern __shared__ char sm[];
    const uint32_t sb = smem_u32(sm);
    const int bh = blockIdx.y, b = bh >> 4, head = bh & 15;
    const int q0 = (int)(gridDim.x - 1 - blockIdx.x) * 64;   // heavy first
    const int tid = threadIdx.x, lane = tid & 31, w = tid >> 5;

    const int* msk = ((head >> 3) == 0 ? mask_head : mask_child)
                     + (size_t)b * SEQ * SEQ;
    float* arcp = arc + (size_t)bh * SEQ * SEQ;

    // per-thread copy coords (512 uint4 per 64x64 tile array; 4 per thread)
    const int crow0 = tid >> 3, cc8 = tid & 7;

    auto load_kv = [&](int kt, int stg) {
        const int k0 = kt * 64;
        const uint32_t base = sb + FKV_BASE + stg * FS_STAGE;
        #pragma unroll
        for (int j = 0; j < 4; j++) {
            int row = crow0 + j * 16;
            uint32_t off = (uint32_t)(row * 144 + cc8 * 16);
            size_t gk = (size_t)(b * SEQ + k0 + row) * 2048
                        + 1024 + head * HD + cc8 * 8;
            cp16(base + FS_KH + off, &g_qkh[gk]);
            cp16(base + FS_KL + off, &g_qkl[gk]);
            size_t gv = ((size_t)bh * 64 + row) * 1024 + k0 + cc8 * 8;
            cp16(base + FS_VH + off, &g_vth[gv]);
            cp16(base + FS_VL + off, &g_vtl[gv]);
        }
    };

    // ---- zero arc above-diagonal region ----
    {
        const int zc4 = (SEQ - q0 - 64) >> 2;
        const float4 z4 = make_float4(0.f, 0.f, 0.f, 0.f);
        for (int i = tid; i < 64 * zc4; i += 128) {
            int r = i / (zc4 ? zc4 : 1), c = i - r * zc4;
            *(float4*)&arcp[(size_t)(q0 + r) * SEQ + q0 + 64 + c * 4] = z4;
        }
    }

    // ---- stage Q (plain copies) + first K/V prefetch ----
    #pragma unroll
    for (int j = 0; j < 4; j++) {
        int row = crow0 + j * 16;
        uint32_t off = (uint32_t)(row * 144 + cc8 * 16);
        size_t g = (size_t)(b * SEQ + q0 + row) * 2048 + head * HD + cc8 * 8;
        *(uint4*)(sm + FQ_H + off) = *(const uint4*)&g_qkh[g];
        *(uint4*)(sm + FQ_L + off) = *(const uint4*)&g_qkl[g];
    }
    load_kv(0, 0);
    CP_COMMIT();

    // ---- online softmax state + O accumulator ----
    const int r0 = lane >> 2;
    float m[2] = {-INFINITY, -INFINITY}, l[2] = {0.f, 0.f};
    float o[8][4] = {};
    uint32_t qhf[4][4], qlf[4][4];

    const int ntiles = q0 / 64 + 1;
    for (int kt = 0; kt < ntiles; kt++) {
        const int k0 = kt * 64;
        if (kt + 1 < ntiles) {
            load_kv(kt + 1, (kt + 1) & 1);
            CP_COMMIT();
            CP_WAIT1();
        } else {
            CP_WAIT0();
        }
        __syncthreads();

        if (kt == 0) {   // preload Q fragments once (Q covered by the bar)
            const int arow = w * 16 + (lane & 15);
            #pragma unroll
            for (int ks = 0; ks < 4; ks++) {
                const int acol = ks * 16 + (lane >> 4) * 8;
                uint32_t ad = (uint32_t)(arow * 144 + acol * 2);
                ldsm4(qhf[ks], sb + FQ_H + ad);
                ldsm4(qlf[ks], sb + FQ_L + ad);
            }
        }

        const uint32_t stg = sb + FKV_BASE + (kt & 1) * FS_STAGE;

        // -- S = Q K^T (m16 x n64, bf16x3) --
        float s[8][4] = {};
        #pragma unroll
        for (int ks = 0; ks < 4; ks++) {
            const int brow = ((lane >> 4) << 3) + (lane & 7);
            const int bcol = ks * 16 + ((lane >> 3) & 1) * 8;
            #pragma unroll
            for (int nf2 = 0; nf2 < 4; nf2++) {
                uint32_t bd = (uint32_t)((nf2 * 16 + brow) * 144 + bcol * 2);
                uint32_t bhf[4], blf[4];
                ldsm4(bhf, stg + FS_KH + bd);
                ldsm4(blf, stg + FS_KL + bd);
                #pragma unroll
                for (int h = 0; h < 2; h++) {
                    float* d = s[nf2 * 2 + h];
                    mma16816(d, qhf[ks], bhf + 2 * h);
                    mma16816(d, qhf[ks], blf + 2 * h);
                    mma16816(d, qlf[ks], bhf + 2 * h);
                }
            }
        }

        // -- epilogue: scale, causal+mask, arc=sigmoid, s=val|-inf --
        #pragma unroll
        for (int half = 0; half < 2; half++) {
            const int qi = q0 + w * 16 + r0 + half * 8;
            #pragma unroll
            for (int nf = 0; nf < 8; nf++) {
                const int kj = k0 + nf * 8 + (lane & 3) * 2;
                const size_t idx = (size_t)qi * SEQ + kj;
                const int2 mv = *(const int2*)&msk[idx];
                float2 og;
                #pragma unroll
                for (int e = 0; e < 2; e++) {
                    float val = s[nf][half * 2 + e] * (1.0f / 64.0f);
                    bool valid = (kj + e <= qi) && ((e ? mv.y : mv.x) != 0);
                    s[nf][half * 2 + e] = valid ? val : -INFINITY;
                    (&og.x)[e] = valid ? 1.0f / (1.0f + __expf(-val)) : 0.0f;
                }
                *(float2*)&arcp[idx] = og;
            }
        }

        // -- online softmax update --
        float alpha[2];
        #pragma unroll
        for (int i = 0; i < 2; i++) {
            float tmax = -INFINITY;
            #pragma unroll
            for (int nf = 0; nf < 8; nf++)
                tmax = fmaxf(tmax, fmaxf(s[nf][i * 2], s[nf][i * 2 + 1]));
            tmax = fmaxf(tmax, __shfl_xor_sync(0xffffffffu, tmax, 1));
            tmax = fmaxf(tmax, __shfl_xor_sync(0xffffffffu, tmax, 2));
            float mnew = fmaxf(m[i], tmax);
            alpha[i] = (m[i] == -INFINITY) ? 0.0f : __expf(m[i] - mnew);
            float tsum = 0.0f;
            #pragma unroll
            for (int nf = 0; nf < 8; nf++) {
                #pragma unroll
                for (int e = 0; e < 2; e++) {
                    float p = (mnew == -INFINITY)
                              ? 0.0f : __expf(s[nf][i * 2 + e] - mnew);
                    s[nf][i * 2 + e] = p;
                    tsum += p;
                }
            }
            tsum += __shfl_xor_sync(0xffffffffu, tsum, 1);
            tsum += __shfl_xor_sync(0xffffffffu, tsum, 2);
            l[i] = l[i] * alpha[i] + tsum;
            m[i] = mnew;
        }
        #pragma unroll
        for (int nf = 0; nf < 8; nf++) {
            o[nf][0] *= alpha[0]; o[nf][1] *= alpha[0];
            o[nf][2] *= alpha[1]; o[nf][3] *= alpha[1];
        }

        // -- P fragments (C-frag -> A-frag identity), hi/lo --
        uint32_t ph[4][4], pl[4][4];
        #pragma unroll
        for (int j = 0; j < 4; j++) {
            const float* e0 = s[2 * j];
            const float* e1 = s[2 * j + 1];
            ph[j][0] = pack_bf16(e0[0], e0[1]);
            split_lo(ph[j][0], e0[0], e0[1], &pl[j][0]);
            ph[j][1] = pack_bf16(e0[2], e0[3]);
            split_lo(ph[j][1], e0[2], e0[3], &pl[j][1]);
            ph[j][2] = pack_bf16(e1[0], e1[1]);
            split_lo(ph[j][2], e1[0], e1[1], &pl[j][2]);
            ph[j][3] = pack_bf16(e1[2], e1[3]);
            split_lo(ph[j][3], e1[2], e1[3], &pl[j][3]);
        }

        // -- O += P V  (m16 n64 k64, bf16x3) --
        #pragma unroll
        for (int j = 0; j < 4; j++) {
            const int brow = ((lane >> 4) << 3) + (lane & 7);
            const int bcol = j * 16 + ((lane >> 3) & 1) * 8;
            #pragma unroll
            for (int nf2 = 0; nf2 < 4; nf2++) {
                uint32_t bd = (uint32_t)((nf2 * 16 + brow) * 144 + bcol * 2);
                uint32_t bhf[4], blf[4];
                ldsm4(bhf, stg + FS_VH + bd);
                ldsm4(blf, stg + FS_VL + bd);
                #pragma unroll
                for (int h = 0; h < 2; h++) {
                    float* d = o[nf2 * 2 + h];
                    mma16816(d, ph[j], bhf + 2 * h);
                    mma16816(d, ph[j], blf + 2 * h);
                    mma16816(d, pl[j], bhf + 2 * h);
                }
            }
        }
        __syncthreads();
    }

    // ---- normalize and write O (bf16 hi/lo for the proj gemm) ----
    const float inv0 = (l[0] > 0.f) ? 1.0f / l[0] : 0.0f;
    const float inv1 = (l[1] > 0.f) ? 1.0f / l[1] : 0.0f;
    const int r = q0 + w * 16 + r0;
    #pragma unroll
    for (int nf = 0; nf < 8; nf++) {
        const int c = head * HD + nf * 8 + (lane & 3) * 2;
        float a0 = o[nf][0] * inv0, a1 = o[nf][1] * inv0;
        uint32_t h = pack_bf16(a0, a1), lo;
        split_lo(h, a0, a1, &lo);
        *(uint32_t*)&g_aoh[(size_t)(b * SEQ + r) * EMB + c] = h;
        *(uint32_t*)&g_aol[(size_t)(b * SEQ + r) * EMB + c] = lo;
        a0 = o[nf][2] * inv1; a1 = o[nf][3] * inv1;
        h = pack_bf16(a0, a1);
        split_lo(h, a0, a1, &lo);
        *(uint32_t*)&g_aoh[(size_t)(b * SEQ + r + 8) * EMB + c] = h;
        *(uint32_t*)&g_aol[(size_t)(b * SEQ + r + 8) * EMB + c] = lo;
    }
}

// ---------------- launch ----------------------------------------------------
extern "C" void kernel_launch(void* const* d_in, const int* in_sizes, int n_in,
                              void* d_out, int out_size) {
    const float* x      = (const float*)d_in[0];
    const float* w_qkv  = (const float*)d_in[1];
    const float* w_proj = (const float*)d_in[2];
    const int*   m_head  = (const int*)d_in[3];
    const int*   m_child = (const int*)d_in[4];

    float* out = (float*)d_out;
    float* arc = out + (size_t)BATCH * SEQ * EMB;

    __nv_bfloat16 *xh, *xl, *wqh, *wql, *wph, *wpl, *aoh, *aol;
    cudaGetSymbolAddress((void**)&xh,  g_xh);
    cudaGetSymbolAddress((void**)&xl,  g_xl);
    cudaGetSymbolAddress((void**)&wqh, g_wqh);
    cudaGetSymbolAddress((void**)&wql, g_wql);
    cudaGetSymbolAddress((void**)&wph, g_wph);
    cudaGetSymbolAddress((void**)&wpl, g_wpl);
    cudaGetSymbolAddress((void**)&aoh, g_aoh);
    cudaGetSymbolAddress((void**)&aol, g_aol);

    cudaFuncSetAttribute(flash_att,
                         cudaFuncAttributeMaxDynamicSharedMemorySize, FO_TOTAL);
    cudaFuncSetAttribute(gemm_pre<0>,
                         cudaFuncAttributeMaxDynamicSharedMemorySize, GS_TOTAL);
    cudaFuncSetAttribute(gemm_pre<1>,
                         cudaFuncAttributeMaxDynamicSharedMemorySize, GS_TOTAL);

    // 0) pre-split inputs to bf16 hi/lo
    split_f32<<<(2048 * 1024) / 1024, 256>>>(x, xh, xl);
    split_f32<<<(3072 * 1024) / 1024, 256>>>(w_qkv, wqh, wql);
    split_f32<<<(1024 * 1024) / 1024, 256>>>(w_proj, wph, wpl);

    // 1) QKV gemm: writes Q|K hi/lo + V transposed hi/lo
    gemm_pre<1><<<dim3(E3 / 64, BATCH * SEQ / 128), 256, GS_TOTAL>>>(
        xh, xl, wqh, wql, nullptr, E3, EMB);

    // 2) fused: scores + mask + sigmoid(arc) + online softmax + P@V
    flash_att<<<dim3(SEQ / 64, BATCH * MHEAD), 128, FO_TOTAL>>>(
        m_head, m_child, arc);

    // 3) out = AO @ Wproj^T  (fp32 epilogue)
    gemm_pre<0><<<dim3(EMB / 64, BATCH * SEQ / 128), 256, GS_TOTAL>>>(
        aoh, aol, wph, wpl, out, EMB, EMB);
}

// round 15
// speedup vs baseline: 1.6653x; 1.6653x over previous
#include <cuda_runtime.h>
#include <cuda_bf16.h>
#include <math.h>
#include <stdint.h>

#define SEQ   1024
#define EMB   1024
#define BATCH 2
#define MHEAD 16      // total heads (M*H)
#define HD    64      // head dim
#define E3    (3*EMB)

// ---------------- scratch (allocation-free rule: __device__ globals) --------
__device__ __nv_bfloat16 g_xh [(size_t)2048*1024], g_xl [(size_t)2048*1024];
__device__ __nv_bfloat16 g_wqh[(size_t)3072*1024], g_wql[(size_t)3072*1024];
__device__ __nv_bfloat16 g_wph[(size_t)1024*1024], g_wpl[(size_t)1024*1024];
__device__ __nv_bfloat16 g_qkh[(size_t)2048*2048], g_qkl[(size_t)2048*2048];  // Q|K
__device__ __nv_bfloat16 g_vth[(size_t)32*64*1024], g_vtl[(size_t)32*64*1024]; // V^T [bh][c][k]
__device__ __nv_bfloat16 g_aoh[(size_t)2048*1024], g_aol[(size_t)2048*1024];

// ===================== helpers ==============================================
__device__ __forceinline__ uint32_t smem_u32(const void* p) {
    uint32_t a;
    asm("{ .reg .u64 t; cvta.to.shared.u64 t, %1; cvt.u32.u64 %0, t; }"
        : "=r"(a) : "l"(p));
    return a;
}
__device__ __forceinline__ void ldsm4(uint32_t* r, uint32_t addr) {
    asm volatile("ldmatrix.sync.aligned.m8n8.x4.shared.b16 {%0,%1,%2,%3}, [%4];"
                 : "=r"(r[0]), "=r"(r[1]), "=r"(r[2]), "=r"(r[3]) : "r"(addr));
}
__device__ __forceinline__ void mma16816(float* d, const uint32_t* a,
                                         const uint32_t* b) {
    asm volatile("mma.sync.aligned.m16n8k16.row.col.f32.bf16.bf16.f32 "
                 "{%0,%1,%2,%3}, {%4,%5,%6,%7}, {%8,%9}, {%0,%1,%2,%3};"
                 : "+f"(d[0]), "+f"(d[1]), "+f"(d[2]), "+f"(d[3])
                 : "r"(a[0]), "r"(a[1]), "r"(a[2]), "r"(a[3]),
                   "r"(b[0]), "r"(b[1]));
}
__device__ __forceinline__ uint32_t pack_bf16(float x, float y) {
    __nv_bfloat162 p;
    p.x = __float2bfloat16(x);
    p.y = __float2bfloat16(y);
    return *(uint32_t*)&p;
}
__device__ __forceinline__ void split_lo(uint32_t hi, float x, float y,
                                         uint32_t* lo) {
    __nv_bfloat162* h = (__nv_bfloat162*)&hi;
    *lo = pack_bf16(x - __bfloat162float(h->x), y - __bfloat162float(h->y));
}

// ---------------- pre-pass: fp32 -> bf16 hi/lo split ------------------------
__global__ void __launch_bounds__(256)
split_f32(const float* __restrict__ s, __nv_bfloat16* __restrict__ h,
          __nv_bfloat16* __restrict__ l) {
    size_t i = ((size_t)blockIdx.x * 256 + threadIdx.x) * 4;
    float4 v = *(const float4*)&s[i];
    uint32_t h0 = pack_bf16(v.x, v.y), h1 = pack_bf16(v.z, v.w);
    uint32_t l0, l1;
    split_lo(h0, v.x, v.y, &l0);
    split_lo(h1, v.z, v.w, &l1);
    *(uint2*)&h[i] = make_uint2(h0, h1);
    *(uint2*)&l[i] = make_uint2(l0, l1);
}

// ========== bf16x3 NT GEMM (pre-split operands): C = A @ B^T ================
// Block tile 128x64, K-chunk 64 (4 k-steps per barrier phase). 8 warps.
// Row stride 72 bf16 = 144B (ldsm conflict-free, proven in flash_att).
// dyn smem: AH 0 (18432), AL 18432, BH 36864 (9216), BL 46080; total 55296
#define GA_H 0
#define GA_L 18432
#define GB_H 36864
#define GB_L 46080
#define GS_TOTAL 55296

template<int EPI>
__global__ void __launch_bounds__(256, 2)
gemm_pre(const __nv_bfloat16* __restrict__ Ah, const __nv_bfloat16* __restrict__ Al,
         const __nv_bfloat16* __restrict__ Bh, const __nv_bfloat16* __restrict__ Bl,
         float* __restrict__ C, int N, int K) {
    extern __shared__ char sm[];
    const uint32_t sb = smem_u32(sm);
    __nv_bfloat16* sAh = (__nv_bfloat16*)(sm + GA_H);
    __nv_bfloat16* sAl = (__nv_bfloat16*)(sm + GA_L);
    __nv_bfloat16* sBh = (__nv_bfloat16*)(sm + GB_H);
    __nv_bfloat16* sBl = (__nv_bfloat16*)(sm + GB_L);
    const int tid = threadIdx.x, lane = tid & 31, wid = tid >> 5;
    const int wm = wid & 3, wn = wid >> 2;
    const int bm = blockIdx.y * 128, bn = blockIdx.x * 64;

    float acc[2][4][4] = {};

    const int nch = K / 64;
    for (int ch = 0; ch < nch; ch++) {
        const int kt = ch * 64;
        // A tile 128x64 bf16: 1024 uint4 per array, 4 per thread
        #pragma unroll
        for (int j = 0; j < 4; j++) {
            int idx = j * 256 + tid;
            int row = idx >> 3, c8 = idx & 7;
            int off = row * 72 + c8 * 8;
            const size_t g = (size_t)(bm + row) * K + kt + c8 * 8;
            *(uint4*)&sAh[off] = *(const uint4*)&Ah[g];
            *(uint4*)&sAl[off] = *(const uint4*)&Al[g];
        }
        // B tile 64x64 bf16: 512 uint4 per array, 2 per thread
        #pragma unroll
        for (int j = 0; j < 2; j++) {
            int idx = j * 256 + tid;
            int row = idx >> 3, c8 = idx & 7;
            int off = row * 72 + c8 * 8;
            const size_t g = (size_t)(bn + row) * K + kt + c8 * 8;
            *(uint4*)&sBh[off] = *(const uint4*)&Bh[g];
            *(uint4*)&sBl[off] = *(const uint4*)&Bl[g];
        }
        __syncthreads();

        #pragma unroll
        for (int ks = 0; ks < 4; ks++) {
            uint32_t ahf[2][4], alf[2][4];
            const int arow = wm * 32 + (lane & 15);
            const int acol = ks * 16 + (lane >> 4) * 8;
            #pragma unroll
            for (int mf = 0; mf < 2; mf++) {
                uint32_t ad = sb + (uint32_t)(((arow + mf * 16) * 72 + acol) * 2);
                ldsm4(ahf[mf], ad + GA_H);
                ldsm4(alf[mf], ad + GA_L);
            }
            const int brow = wn * 32 + ((lane >> 4) << 3) + (lane & 7);
            const int bcol = ks * 16 + ((lane >> 3) & 1) * 8;
            #pragma unroll
            for (int nf2 = 0; nf2 < 2; nf2++) {
                uint32_t bd = sb + (uint32_t)(((brow + nf2 * 16) * 72 + bcol) * 2);
                uint32_t bhf[4], blf[4];
                ldsm4(bhf, bd + GB_H);
                ldsm4(blf, bd + GB_L);
                #pragma unroll
                for (int h = 0; h < 2; h++) {
                    #pragma unroll
                    for (int mf = 0; mf < 2; mf++) {
                        float* d = acc[mf][nf2 * 2 + h];
                        mma16816(d, ahf[mf], bhf + 2 * h);
                        mma16816(d, ahf[mf], blf + 2 * h);
                        mma16816(d, alf[mf], bhf + 2 * h);
                    }
                }
            }
        }
        __syncthreads();
    }

    if (EPI == 0) {
        // fp32 C
        #pragma unroll
        for (int mf = 0; mf < 2; mf++) {
            const int r = bm + wm * 32 + mf * 16 + (lane >> 2);
            #pragma unroll
            for (int nf = 0; nf < 4; nf++) {
                const int c = bn + wn * 32 + nf * 8 + (lane & 3) * 2;
                *(float2*)&C[(size_t)r * N + c] =
                    make_float2(acc[mf][nf][0], acc[mf][nf][1]);
                *(float2*)&C[(size_t)(r + 8) * N + c] =
                    make_float2(acc[mf][nf][2], acc[mf][nf][3]);
            }
        }
    } else if (bn < 2048) {
        // Q|K region: hi/lo bf16, row stride 2048
        #pragma unroll
        for (int mf = 0; mf < 2; mf++) {
            const int r = bm + wm * 32 + mf * 16 + (lane >> 2);
            #pragma unroll
            for (int nf = 0; nf < 4; nf++) {
                const int c = bn + wn * 32 + nf * 8 + (lane & 3) * 2;
                float a0 = acc[mf][nf][0], a1 = acc[mf][nf][1];
                uint32_t h = pack_bf16(a0, a1), lo;
                split_lo(h, a0, a1, &lo);
                *(uint32_t*)&g_qkh[(size_t)r * 2048 + c] = h;
                *(uint32_t*)&g_qkl[(size_t)r * 2048 + c] = lo;
                a0 = acc[mf][nf][2]; a1 = acc[mf][nf][3];
                h = pack_bf16(a0, a1);
                split_lo(h, a0, a1, &lo);
                *(uint32_t*)&g_qkh[(size_t)(r + 8) * 2048 + c] = h;
                *(uint32_t*)&g_qkl[(size_t)(r + 8) * 2048 + c] = lo;
            }
        }
    } else {
        // V region: write transposed hi/lo  g_vt[bh][c][k]
        #pragma unroll
        for (int mf = 0; mf < 2; mf++) {
            const int r = bm + wm * 32 + mf * 16 + (lane >> 2);
            const int bnum = r >> 10, k1 = r & 1023, k2 = (r + 8) & 1023;
            #pragma unroll
            for (int nf = 0; nf < 4; nf++) {
                #pragma unroll
                for (int e = 0; e < 2; e++) {
                    const int cm = bn + wn * 32 + nf * 8 + (lane & 3) * 2 + e
                                   - 2048;
                    const size_t rb =
                        ((size_t)(bnum * 16 + (cm >> 6)) * 64 + (cm & 63)) * 1024;
                    float v0 = acc[mf][nf][e], v1 = acc[mf][nf][2 + e];
                    __nv_bfloat16 h0 = __float2bfloat16(v0);
                    g_vth[rb + k1] = h0;
                    g_vtl[rb + k1] =
                        __float2bfloat16(v0 - __bfloat162float(h0));
                    __nv_bfloat16 h1 = __float2bfloat16(v1);
                    g_vth[rb + k2] = h1;
                    g_vtl[rb + k2] =
                        __float2bfloat16(v1 - __bfloat162float(h1));
                }
            }
        }
    }
}

// ========== fused flash attention (S = QK^T/64, mask, arc, softmax, PV) =====
// grid (S/64 q-tiles, B*MHEAD), 128 threads (4 warps x 16 q-rows).
// All staging is raw bf16 copies (operands pre-split; V pre-transposed).
#define SQPAD 72            // rows: 64 cols + 8 pad (bf16), 144B stride
#define FO_QH 0
#define FO_QL 9216
#define FO_KH 18432
#define FO_KL 27648
#define FO_VH 36864
#define FO_VL 46080
#define FO_TOTAL 55296

__global__ void __launch_bounds__(128, 3)
flash_att(const int* __restrict__ mask_head, const int* __restrict__ mask_child,
          float* __restrict__ arc) {
    extern __shared__ char sm[];
    const int bh = blockIdx.y, b = bh >> 4, head = bh & 15;
    const int q0 = (int)(gridDim.x - 1 - blockIdx.x) * 64;   // heavy first
    const int tid = threadIdx.x, lane = tid & 31, w = tid >> 5;

    __nv_bfloat16* sQh = (__nv_bfloat16*)(sm + FO_QH);
    __nv_bfloat16* sQl = (__nv_bfloat16*)(sm + FO_QL);
    __nv_bfloat16* sKh = (__nv_bfloat16*)(sm + FO_KH);
    __nv_bfloat16* sKl = (__nv_bfloat16*)(sm + FO_KL);
    __nv_bfloat16* sVh = (__nv_bfloat16*)(sm + FO_VH);
    __nv_bfloat16* sVl = (__nv_bfloat16*)(sm + FO_VL);
    const uint32_t sb_qh = smem_u32(sQh), sb_ql = smem_u32(sQl);
    const uint32_t sb_kh = smem_u32(sKh), sb_kl = smem_u32(sKl);
    const uint32_t sb_vh = smem_u32(sVh), sb_vl = smem_u32(sVl);

    const int* msk = ((head >> 3) == 0 ? mask_head : mask_child)
                     + (size_t)b * SEQ * SEQ;
    float* arcp = arc + (size_t)bh * SEQ * SEQ;

    // ---- zero arc above-diagonal region: rows q0..q0+63, cols q0+64.. ----
    {
        const int zc4 = (SEQ - q0 - 64) >> 2;         // float4 per row
        const float4 z4 = make_float4(0.f, 0.f, 0.f, 0.f);
        for (int i = tid; i < 64 * zc4; i += 128) {
            int r = i / (zc4 ? zc4 : 1), c = i - r * zc4;
            *(float4*)&arcp[(size_t)(q0 + r) * SEQ + q0 + 64 + c * 4] = z4;
        }
    }

    // ---- stage Q (64 x 64 bf16 hi/lo): 512 uint4 per array ----
    #pragma unroll
    for (int j = 0; j < 4; j++) {
        int idx = j * 128 + tid;                      // 0..511
        int row = idx >> 3, c8 = idx & 7;
        int off = row * SQPAD + c8 * 8;
        size_t g = (size_t)(b * SEQ + q0 + row) * 2048 + head * HD + c8 * 8;
        *(uint4*)&sQh[off] = *(const uint4*)&g_qkh[g];
        *(uint4*)&sQl[off] = *(const uint4*)&g_qkl[g];
    }
    __syncthreads();

    // ---- preload Q fragments (loop-invariant): 4 k-steps, hi/lo ----
    uint32_t qhf[4][4], qlf[4][4];
    {
        const int arow = w * 16 + (lane & 15);
        #pragma unroll
        for (int ks = 0; ks < 4; ks++) {
            const int acol = ks * 16 + (lane >> 4) * 8;
            uint32_t ad = (uint32_t)((arow * SQPAD + acol) * 2);
            ldsm4(qhf[ks], sb_qh + ad);
            ldsm4(qlf[ks], sb_ql + ad);
        }
    }

    // ---- online softmax state (per thread: 2 rows) + O accumulator ----
    const int r0 = lane >> 2;                // rows w*16 + r0, + r0+8
    float m[2] = {-INFINITY, -INFINITY}, l[2] = {0.f, 0.f};
    float o[8][4] = {};                      // m16 n64 output frags

    const int ntiles = q0 / 64 + 1;          // causal: cols < q0+64
    for (int kt = 0; kt < ntiles; kt++) {
        const int k0 = kt * 64;
        // -- stage K tile (64x64 hi/lo): 512 uint4 per array --
        #pragma unroll
        for (int j = 0; j < 4; j++) {
            int idx = j * 128 + tid;
            int row = idx >> 3, c8 = idx & 7;
            int off = row * SQPAD + c8 * 8;
            size_t g = (size_t)(b * SEQ + k0 + row) * 2048
                       + 1024 + head * HD + c8 * 8;
            *(uint4*)&sKh[off] = *(const uint4*)&g_qkh[g];
            *(uint4*)&sKl[off] = *(const uint4*)&g_qkl[g];
        }
        // -- stage V tile (pre-transposed [c][k]): 512 uint4 per array --
        #pragma unroll
        for (int j = 0; j < 4; j++) {
            int idx = j * 128 + tid;
            int row = idx >> 3, k8 = idx & 7;
            int off = row * SQPAD + k8 * 8;
            size_t g = ((size_t)bh * 64 + row) * 1024 + k0 + k8 * 8;
            *(uint4*)&sVh[off] = *(const uint4*)&g_vth[g];
            *(uint4*)&sVl[off] = *(const uint4*)&g_vtl[g];
        }
        __syncthreads();

        // -- S = Q K^T (m16 x n64, bf16x3) --
        float s[8][4] = {};
        #pragma unroll
        for (int ks = 0; ks < 4; ks++) {
            const int brow = ((lane >> 4) << 3) + (lane & 7);
            const int bcol = ks * 16 + ((lane >> 3) & 1) * 8;
            #pragma unroll
            for (int nf2 = 0; nf2 < 4; nf2++) {
                uint32_t bd = (uint32_t)(((nf2 * 16 + brow) * SQPAD + bcol) * 2);
                uint32_t bhf[4], blf[4];
                ldsm4(bhf, sb_kh + bd);
                ldsm4(blf, sb_kl + bd);
                #pragma unroll
                for (int h = 0; h < 2; h++) {
                    float* d = s[nf2 * 2 + h];
                    mma16816(d, qhf[ks], bhf + 2 * h);
                    mma16816(d, qhf[ks], blf + 2 * h);
                    mma16816(d, qlf[ks], bhf + 2 * h);
                }
            }
        }

        // -- epilogue: scale, causal+mask, arc=sigmoid, s=val|-inf --
        #pragma unroll
        for (int half = 0; half < 2; half++) {
            const int qi = q0 + w * 16 + r0 + half * 8;
            #pragma unroll
            for (int nf = 0; nf < 8; nf++) {
                const int kj = k0 + nf * 8 + (lane & 3) * 2;
                const size_t idx = (size_t)qi * SEQ + kj;
                const int2 mv = *(const int2*)&msk[idx];
                float2 og;
                #pragma unroll
                for (int e = 0; e < 2; e++) {
                    float val = s[nf][half * 2 + e] * (1.0f / 64.0f);
                    bool valid = (kj + e <= qi) && ((e ? mv.y : mv.x) != 0);
                    s[nf][half * 2 + e] = valid ? val : -INFINITY;
                    (&og.x)[e] = valid ? 1.0f / (1.0f + __expf(-val)) : 0.0f;
                }
                *(float2*)&arcp[idx] = og;
            }
        }

        // -- online softmax update --
        float alpha[2];
        #pragma unroll
        for (int i = 0; i < 2; i++) {
            float tmax = -INFINITY;
            #pragma unroll
            for (int nf = 0; nf < 8; nf++)
                tmax = fmaxf(tmax, fmaxf(s[nf][i * 2], s[nf][i * 2 + 1]));
            tmax = fmaxf(tmax, __shfl_xor_sync(0xffffffffu, tmax, 1));
            tmax = fmaxf(tmax, __shfl_xor_sync(0xffffffffu, tmax, 2));
            float mnew = fmaxf(m[i], tmax);
            alpha[i] = (m[i] == -INFINITY) ? 0.0f : __expf(m[i] - mnew);
            float tsum = 0.0f;
            #pragma unroll
            for (int nf = 0; nf < 8; nf++) {
                #pragma unroll
                for (int e = 0; e < 2; e++) {
                    float p = (mnew == -INFINITY)
                              ? 0.0f : __expf(s[nf][i * 2 + e] - mnew);
                    s[nf][i * 2 + e] = p;
                    tsum += p;
                }
            }
            tsum += __shfl_xor_sync(0xffffffffu, tsum, 1);
            tsum += __shfl_xor_sync(0xffffffffu, tsum, 2);
            l[i] = l[i] * alpha[i] + tsum;
            m[i] = mnew;
        }
        #pragma unroll
        for (int nf = 0; nf < 8; nf++) {
            o[nf][0] *= alpha[0]; o[nf][1] *= alpha[0];
            o[nf][2] *= alpha[1]; o[nf][3] *= alpha[1];
        }

        // -- P fragments (C-frag -> A-frag identity), hi/lo --
        uint32_t ph[4][4], pl[4][4];
        #pragma unroll
        for (int j = 0; j < 4; j++) {
            const float* e0 = s[2 * j];      // k = j*16 + (lane&3)*2 (+1)
            const float* e1 = s[2 * j + 1];  // k = +8
            ph[j][0] = pack_bf16(e0[0], e0[1]);
            split_lo(ph[j][0], e0[0], e0[1], &pl[j][0]);
            ph[j][1] = pack_bf16(e0[2], e0[3]);
            split_lo(ph[j][1], e0[2], e0[3], &pl[j][1]);
            ph[j][2] = pack_bf16(e1[0], e1[1]);
            split_lo(ph[j][2], e1[0], e1[1], &pl[j][2]);
            ph[j][3] = pack_bf16(e1[2], e1[3]);
            split_lo(ph[j][3], e1[2], e1[3], &pl[j][3]);
        }

        // -- O += P V  (m16 n64 k64, bf16x3) --
        #pragma unroll
        for (int j = 0; j < 4; j++) {        // k-steps over P's 64 keys
            const int brow = ((lane >> 4) << 3) + (lane & 7);
            const int bcol = j * 16 + ((lane >> 3) & 1) * 8;
            #pragma unroll
            for (int nf2 = 0; nf2 < 4; nf2++) {
                uint32_t bd = (uint32_t)(((nf2 * 16 + brow) * SQPAD + bcol) * 2);
                uint32_t bhf[4], blf[4];
                ldsm4(bhf, sb_vh + bd);
                ldsm4(blf, sb_vl + bd);
                #pragma unroll
                for (int h = 0; h < 2; h++) {
                    float* d = o[nf2 * 2 + h];
                    mma16816(d, ph[j], bhf + 2 * h);
                    mma16816(d, ph[j], blf + 2 * h);
                    mma16816(d, pl[j], bhf + 2 * h);
                }
            }
        }
        __syncthreads();
    }

    // ---- normalize and write O (bf16 hi/lo for the proj gemm) ----
    const float inv0 = (l[0] > 0.f) ? 1.0f / l[0] : 0.0f;
    const float inv1 = (l[1] > 0.f) ? 1.0f / l[1] : 0.0f;
    const int r = q0 + w * 16 + r0;
    #pragma unroll
    for (int nf = 0; nf < 8; nf++) {
        const int c = head * HD + nf * 8 + (lane & 3) * 2;
        float a0 = o[nf][0] * inv0, a1 = o[nf][1] * inv0;
        uint32_t h = pack_bf16(a0, a1), lo;
        split_lo(h, a0, a1, &lo);
        *(uint32_t*)&g_aoh[(size_t)(b * SEQ + r) * EMB + c] = h;
        *(uint32_t*)&g_aol[(size_t)(b * SEQ + r) * EMB + c] = lo;
        a0 = o[nf][2] * inv1; a1 = o[nf][3] * inv1;
        h = pack_bf16(a0, a1);
        split_lo(h, a0, a1, &lo);
        *(uint32_t*)&g_aoh[(size_t)(b * SEQ + r + 8) * EMB + c] = h;
        *(uint32_t*)&g_aol[(size_t)(b * SEQ + r + 8) * EMB + c] = lo;
    }
}

// ---------------- launch ----------------------------------------------------
extern "C" void kernel_launch(void* const* d_in, const int* in_sizes, int n_in,
                              void* d_out, int out_size) {
    const float* x      = (const float*)d_in[0];
    const float* w_qkv  = (const float*)d_in[1];
    const float* w_proj = (const float*)d_in[2];
    const int*   m_head  = (const int*)d_in[3];
    const int*   m_child = (const int*)d_in[4];

    float* out = (float*)d_out;
    float* arc = out + (size_t)BATCH * SEQ * EMB;

    __nv_bfloat16 *xh, *xl, *wqh, *wql, *wph, *wpl, *aoh, *aol;
    cudaGetSymbolAddress((void**)&xh,  g_xh);
    cudaGetSymbolAddress((void**)&xl,  g_xl);
    cudaGetSymbolAddress((void**)&wqh, g_wqh);
    cudaGetSymbolAddress((void**)&wql, g_wql);
    cudaGetSymbolAddress((void**)&wph, g_wph);
    cudaGetSymbolAddress((void**)&wpl, g_wpl);
    cudaGetSymbolAddress((void**)&aoh, g_aoh);
    cudaGetSymbolAddress((void**)&aol, g_aol);

    cudaFuncSetAttribute(flash_att,
                         cudaFuncAttributeMaxDynamicSharedMemorySize, FO_TOTAL);
    cudaFuncSetAttribute(gemm_pre<0>,
                         cudaFuncAttributeMaxDynamicSharedMemorySize, GS_TOTAL);
    cudaFuncSetAttribute(gemm_pre<1>,
                         cudaFuncAttributeMaxDynamicSharedMemorySize, GS_TOTAL);

    // 0) pre-split inputs to bf16 hi/lo (once per call; tiny)
    split_f32<<<(2048 * 1024) / 1024, 256>>>(x, xh, xl);
    split_f32<<<(3072 * 1024) / 1024, 256>>>(w_qkv, wqh, wql);
    split_f32<<<(1024 * 1024) / 1024, 256>>>(w_proj, wph, wpl);

    // 1) QKV gemm: writes Q|K hi/lo + V transposed hi/lo
    gemm_pre<1><<<dim3(E3 / 64, BATCH * SEQ / 128), 256, GS_TOTAL>>>(
        xh, xl, wqh, wql, nullptr, E3, EMB);

    // 2) fused: scores + mask + sigmoid(arc) + online softmax + P@V
    flash_att<<<dim3(SEQ / 64, BATCH * MHEAD), 128, FO_TOTAL>>>(
        m_head, m_child, arc);

    // 3) out = AO @ Wproj^T  (fp32 epilogue)
    gemm_pre<0><<<dim3(EMB / 64, BATCH * SEQ / 128), 256, GS_TOTAL>>>(
        aoh, aol, wph, wpl, out, EMB, EMB);
}